// round 5
// baseline (speedup 1.0000x reference)
#include <cuda_runtime.h>
#include <cstdint>
#include <math.h>

#define S_LEN 2048
#define D_MOD 1024
#define ROWS  4096          // B*S
#define NBH   32            // B*H

// ---------------- scratch (static; no allocations) ----------
__device__ __align__(128) float g_Q  [NBH * S_LEN * 64];
__device__ __align__(128) float g_K  [NBH * S_LEN * 64];
__device__ __align__(128) float g_V  [NBH * S_LEN * 64];
__device__ __align__(128) float g_Vt [NBH * 64 * S_LEN];    // [bh][dk][s]
__device__ __align__(128) float g_ctx[ROWS * D_MOD];
__device__ __align__(128) float g_prj[ROWS * D_MOD];
__device__ __align__(128) float g_WqkvT[3 * D_MOD * D_MOD]; // [3072][1024] K-major
__device__ __align__(128) float g_WoT  [D_MOD * D_MOD];

// ---------------- helpers ----------------
__device__ __forceinline__ uint32_t smem_u32(const void* p) {
    uint32_t a;
    asm("{ .reg .u64 t; cvta.to.shared.u64 t, %1; cvt.u32.u64 %0, t; }" : "=r"(a) : "l"(p));
    return a;
}
__device__ __forceinline__ float to_tf32r(float x) {
    uint32_t u;
    asm("cvt.rna.tf32.f32 %0, %1;" : "=r"(u) : "f"(x));
    return __uint_as_float(u);
}
__device__ __forceinline__ void cp16(uint32_t dst, const void* src) {
    asm volatile("cp.async.cg.shared.global [%0], [%1], 16;" :: "r"(dst), "l"(src) : "memory");
}
#define CP_COMMIT() asm volatile("cp.async.commit_group;" ::: "memory")
#define CP_WAIT0()  asm volatile("cp.async.wait_group 0;" ::: "memory")
#define CP_WAIT1()  asm volatile("cp.async.wait_group 1;" ::: "memory")

// D += A@B, m16n8k8 tf32 (A row-major, B col-major i.e. stored [n][k])
__device__ __forceinline__ void mma8(float* d, const uint32_t* a, const uint32_t* b) {
    asm volatile("mma.sync.aligned.m16n8k8.row.col.f32.tf32.tf32.f32 "
        "{%0,%1,%2,%3}, {%4,%5,%6,%7}, {%8,%9}, {%0,%1,%2,%3};"
        : "+f"(d[0]), "+f"(d[1]), "+f"(d[2]), "+f"(d[3])
        : "r"(a[0]), "r"(a[1]), "r"(a[2]), "r"(a[3]), "r"(b[0]), "r"(b[1]));
}

// ======================= tf32 mma.sync GEMM =======================
// C[4096, N] = A[4096,1024] @ W[N,1024]^T + bias.  BM=BN=128, BK=16.
#define GPAD 20

template <int QKV>
__global__ __launch_bounds__(256, 2) void gemm_mma(
    const float* __restrict__ A, const float* __restrict__ W,
    const float* __restrict__ b0, const float* __restrict__ b1, const float* __restrict__ b2,
    float* __restrict__ o0, float* __restrict__ o1, float* __restrict__ o2)
{
    __shared__ float As[2][128 * GPAD];
    __shared__ float Bs[2][128 * GPAD];

    const int tid = threadIdx.x;
    const int wid = tid >> 5, lane = tid & 31;
    const int g = lane >> 2, t = lane & 3;
    const int wm = wid & 1, wn = wid >> 1;       // warp 64 (M) x 32 (N)
    const int m0 = blockIdx.y * 128;
    const int n0 = blockIdx.x * 128;

    const uint32_t sA[2] = {smem_u32(As[0]), smem_u32(As[1])};
    const uint32_t sB[2] = {smem_u32(Bs[0]), smem_u32(Bs[1])};

    float acc[4][4][4];
#pragma unroll
    for (int i = 0; i < 4; i++)
#pragma unroll
        for (int j = 0; j < 4; j++)
#pragma unroll
            for (int r = 0; r < 4; r++) acc[i][j][r] = 0.f;

#define G_LOAD(st, kt) do {                                                       \
    _Pragma("unroll")                                                             \
    for (int i = 0; i < 2; i++) {                                                 \
        int j = tid + i * 256;                                                    \
        int r = j >> 2, c = (j & 3) * 4;                                          \
        cp16(sA[st] + (uint32_t)(r * GPAD + c) * 4,                               \
             A + (size_t)(m0 + r) * 1024 + (kt) * 16 + c);                        \
        cp16(sB[st] + (uint32_t)(r * GPAD + c) * 4,                               \
             W + (size_t)(n0 + r) * 1024 + (kt) * 16 + c);                        \
    }                                                                             \
    CP_COMMIT();                                                                  \
} while (0)

    G_LOAD(0, 0);
    for (int kt = 0; kt < 64; kt++) {
        const int st = kt & 1;
        if (kt < 63) { G_LOAD(st ^ 1, kt + 1); CP_WAIT1(); }
        else         { CP_WAIT0(); }
        __syncthreads();

        const float* Ab = As[st];
        const float* Bb = Bs[st];
#pragma unroll
        for (int ks = 0; ks < 2; ks++) {
            uint32_t af[4][4];
#pragma unroll
            for (int mt = 0; mt < 4; mt++) {
                const float* ap = Ab + (wm * 64 + mt * 16 + g) * GPAD + ks * 8 + t;
                af[mt][0] = __float_as_uint(ap[0]);
                af[mt][1] = __float_as_uint(ap[8 * GPAD]);
                af[mt][2] = __float_as_uint(ap[4]);
                af[mt][3] = __float_as_uint(ap[8 * GPAD + 4]);
            }
#pragma unroll
            for (int nt = 0; nt < 4; nt++) {
                const float* bp = Bb + (wn * 32 + nt * 8 + g) * GPAD + ks * 8 + t;
                uint32_t bf[2] = {__float_as_uint(bp[0]), __float_as_uint(bp[4])};
#pragma unroll
                for (int mt = 0; mt < 4; mt++) mma8(acc[mt][nt], af[mt], bf);
            }
        }
        __syncthreads();
    }

    // epilogue
#pragma unroll
    for (int mt = 0; mt < 4; mt++) {
        const int r0 = m0 + wm * 64 + mt * 16 + g;
#pragma unroll
        for (int nt = 0; nt < 4; nt++) {
            const int col = n0 + wn * 32 + nt * 8 + 2 * t;
            if (QKV) {
                const int mat = col >> 10, nl = col & 1023;
                const float* bias = (mat == 0 ? b0 : mat == 1 ? b1 : b2);
                float* op = (mat == 0 ? o0 : mat == 1 ? o1 : o2);
                const int h = nl >> 6, d = nl & 63;
                const float2 bv = *(const float2*)(bias + nl);
                const int b = r0 >> 11, s = r0 & 2047;
                float* p = op + ((size_t)((b * 16 + h) * 2048 + s)) * 64 + d;
                *(float2*)p = make_float2(to_tf32r(acc[mt][nt][0] + bv.x),
                                          to_tf32r(acc[mt][nt][1] + bv.y));
                *(float2*)(p + 8 * 64) = make_float2(to_tf32r(acc[mt][nt][2] + bv.x),
                                                     to_tf32r(acc[mt][nt][3] + bv.y));
            } else {
                const float2 bv = *(const float2*)(b0 + col);
                float* p = o0 + (size_t)r0 * 1024 + col;
                *(float2*)p = make_float2(acc[mt][nt][0] + bv.x, acc[mt][nt][1] + bv.y);
                *(float2*)(p + 8 * 1024) = make_float2(acc[mt][nt][2] + bv.x,
                                                       acc[mt][nt][3] + bv.y);
            }
        }
    }
}

// ======================= attention on mma.sync =======================
// CTA: 128 queries of one (b,h), 8 warps (16 q-rows each). KV tiles of 64.
#define APAD 68
#define QTILE  (128 * APAD)           // floats
#define KVTILE (64 * APAD)            // floats per stage

__global__ __launch_bounds__(256, 1) void attn_tc(
    const float* __restrict__ Q, const float* __restrict__ K,
    const float* __restrict__ Vt, float* __restrict__ Ctx)
{
    extern __shared__ float sm[];
    float* Qs = sm;                         // [128][68]
    float* Ps = sm + QTILE;                 // [128][68]
    float* Ks = sm + 2 * QTILE;             // [2][64][68]
    float* Vs = sm + 2 * QTILE + 2 * KVTILE;// [2][64][68] (V^T: rows=dk, cols=key)

    const int bh = blockIdx.y;
    const int q0 = blockIdx.x * 128;
    const int tid = threadIdx.x;
    const int wid = tid >> 5, lane = tid & 31;
    const int g = lane >> 2, t = lane & 3;

    const float* Qb = Q  + (size_t)bh * S_LEN * 64;
    const float* Kb = K  + (size_t)bh * S_LEN * 64;
    const float* Vb = Vt + (size_t)bh * 64 * S_LEN;

    const uint32_t uQ = smem_u32(Qs);
    const uint32_t uK[2] = {smem_u32(Ks), smem_u32(Ks + KVTILE)};
    const uint32_t uV[2] = {smem_u32(Vs), smem_u32(Vs + KVTILE)};

#define LOAD_K(st, kt) do { _Pragma("unroll") for (int i = 0; i < 4; i++) { \
    int j = tid + i * 256; int r = j >> 4, c = (j & 15) * 4;                \
    cp16(uK[st] + (uint32_t)(r * APAD + c) * 4,                             \
         Kb + (size_t)((kt) * 64 + r) * 64 + c); } } while (0)
#define LOAD_V(st, kt) do { _Pragma("unroll") for (int i = 0; i < 4; i++) { \
    int j = tid + i * 256; int r = j >> 4, c = (j & 15) * 4;                \
    cp16(uV[st] + (uint32_t)(r * APAD + c) * 4,                             \
         Vb + (size_t)r * S_LEN + (kt) * 64 + c); } } while (0)

    // prologue: Q + K0 + V0 in one group
#pragma unroll
    for (int i = 0; i < 8; i++) {
        int j = tid + i * 256; int r = j >> 4, c = (j & 15) * 4;
        cp16(uQ + (uint32_t)(r * APAD + c) * 4, Qb + (size_t)(q0 + r) * 64 + c);
    }
    LOAD_K(0, 0); LOAD_V(0, 0); CP_COMMIT();

    float m0 = -1e30f, m1 = -1e30f, l0 = 0.f, l1 = 0.f;
    float oacc[8][4];
#pragma unroll
    for (int i = 0; i < 8; i++)
#pragma unroll
        for (int r = 0; r < 4; r++) oacc[i][r] = 0.f;

    const int rbase = wid * 16 + g;           // this thread's q-row (local, 0..127)

    for (int kt = 0; kt < 32; kt++) {
        const int st = kt & 1;
        CP_WAIT0();
        __syncthreads();
        if (kt < 31) { LOAD_K(st ^ 1, kt + 1); LOAD_V(st ^ 1, kt + 1); CP_COMMIT(); }

        // ---- scores S = Q @ K^T over dk=64 ----
        float sacc[8][4];
#pragma unroll
        for (int i = 0; i < 8; i++)
#pragma unroll
            for (int r = 0; r < 4; r++) sacc[i][r] = 0.f;

        const float* Kt = Ks + st * KVTILE;
#pragma unroll
        for (int ks = 0; ks < 8; ks++) {
            const float* ap = Qs + rbase * APAD + ks * 8 + t;
            uint32_t af[4] = {__float_as_uint(ap[0]), __float_as_uint(ap[8 * APAD]),
                              __float_as_uint(ap[4]), __float_as_uint(ap[8 * APAD + 4])};
#pragma unroll
            for (int nt = 0; nt < 8; nt++) {
                const float* bp = Kt + (nt * 8 + g) * APAD + ks * 8 + t;
                uint32_t bf[2] = {__float_as_uint(bp[0]), __float_as_uint(bp[4])};
                mma8(sacc[nt], af, bf);
            }
        }

        // ---- online softmax (rows rbase, rbase+8) ----
        float rmax0 = -1e30f, rmax1 = -1e30f;
#pragma unroll
        for (int nt = 0; nt < 8; nt++) {
#pragma unroll
            for (int r = 0; r < 4; r++) sacc[nt][r] *= 0.125f;
            rmax0 = fmaxf(rmax0, fmaxf(sacc[nt][0], sacc[nt][1]));
            rmax1 = fmaxf(rmax1, fmaxf(sacc[nt][2], sacc[nt][3]));
        }
        rmax0 = fmaxf(rmax0, __shfl_xor_sync(0xffffffffu, rmax0, 1));
        rmax0 = fmaxf(rmax0, __shfl_xor_sync(0xffffffffu, rmax0, 2));
        rmax1 = fmaxf(rmax1, __shfl_xor_sync(0xffffffffu, rmax1, 1));
        rmax1 = fmaxf(rmax1, __shfl_xor_sync(0xffffffffu, rmax1, 2));

        const float mn0 = fmaxf(m0, rmax0), mn1 = fmaxf(m1, rmax1);
        const float f0 = __expf(m0 - mn0), f1 = __expf(m1 - mn1);
        m0 = mn0; m1 = mn1;

        float rs0 = 0.f, rs1 = 0.f;
#pragma unroll
        for (int nt = 0; nt < 8; nt++) {
            const float p00 = to_tf32r(__expf(sacc[nt][0] - m0));
            const float p01 = to_tf32r(__expf(sacc[nt][1] - m0));
            const float p10 = to_tf32r(__expf(sacc[nt][2] - m1));
            const float p11 = to_tf32r(__expf(sacc[nt][3] - m1));
            rs0 += p00 + p01; rs1 += p10 + p11;
            *(float2*)&Ps[rbase * APAD + nt * 8 + 2 * t]       = make_float2(p00, p01);
            *(float2*)&Ps[(rbase + 8) * APAD + nt * 8 + 2 * t] = make_float2(p10, p11);
        }
        rs0 += __shfl_xor_sync(0xffffffffu, rs0, 1);
        rs0 += __shfl_xor_sync(0xffffffffu, rs0, 2);
        rs1 += __shfl_xor_sync(0xffffffffu, rs1, 1);
        rs1 += __shfl_xor_sync(0xffffffffu, rs1, 2);
        l0 = l0 * f0 + rs0; l1 = l1 * f1 + rs1;

#pragma unroll
        for (int nt = 0; nt < 8; nt++) {
            oacc[nt][0] *= f0; oacc[nt][1] *= f0;
            oacc[nt][2] *= f1; oacc[nt][3] *= f1;
        }
        __syncwarp();   // Ps rows are per-warp private

        // ---- O += P @ V  (V^T layout [dk][key]) ----
        const float* Vtile = Vs + st * KVTILE;
#pragma unroll
        for (int ks = 0; ks < 8; ks++) {
            const float* ap = Ps + rbase * APAD + ks * 8 + t;
            uint32_t af[4] = {__float_as_uint(ap[0]), __float_as_uint(ap[8 * APAD]),
                              __float_as_uint(ap[4]), __float_as_uint(ap[8 * APAD + 4])};
#pragma unroll
            for (int nt = 0; nt < 8; nt++) {
                const float* bp = Vtile + (nt * 8 + g) * APAD + ks * 8 + t;
                uint32_t bf[2] = {__float_as_uint(bp[0]), __float_as_uint(bp[4])};
                mma8(oacc[nt], af, bf);
            }
        }
        __syncwarp();
    }

    // ---- epilogue: ctx[b][s][h*64+d], tf32-rounded for the out-proj GEMM ----
    const float inv0 = 1.f / l0, inv1 = 1.f / l1;
    const int b = bh >> 4, h = bh & 15;
    const int row0 = q0 + rbase;
    float* base0 = Ctx + ((size_t)(b * 2048 + row0)) * 1024 + h * 64;
#pragma unroll
    for (int nt = 0; nt < 8; nt++) {
        const int col = nt * 8 + 2 * t;
        *(float2*)(base0 + col) = make_float2(to_tf32r(oacc[nt][0] * inv0),
                                              to_tf32r(oacc[nt][1] * inv0));
        *(float2*)(base0 + 8 * 1024 + col) = make_float2(to_tf32r(oacc[nt][2] * inv1),
                                                         to_tf32r(oacc[nt][3] * inv1));
    }
}

// ======================= prep kernels =======================
__global__ __launch_bounds__(256) void prep_weights(
    const float* __restrict__ Wq, const float* __restrict__ Wk,
    const float* __restrict__ Wv, const float* __restrict__ Wo,
    float* __restrict__ WqkvT, float* __restrict__ WoT)
{
    __shared__ float tb[32][33];
    const int z = blockIdx.z;
    const float* src = (z == 0) ? Wq : (z == 1) ? Wk : (z == 2) ? Wv : Wo;
    float* dst = (z < 3) ? (WqkvT + (size_t)z * D_MOD * D_MOD) : WoT;
    const int k0 = blockIdx.x * 32, n0 = blockIdx.y * 32;
    const int tx = threadIdx.x, ty = threadIdx.y;   // 32 x 8
#pragma unroll
    for (int i = 0; i < 4; i++)
        tb[ty + i * 8][tx] = src[(size_t)(k0 + ty + i * 8) * D_MOD + n0 + tx];
    __syncthreads();
#pragma unroll
    for (int i = 0; i < 4; i++)
        dst[(size_t)(n0 + ty + i * 8) * D_MOD + k0 + tx] = to_tf32r(tb[tx][ty + i * 8]);
}

// V [bh][s][64] -> Vt [bh][64][s]
__global__ __launch_bounds__(256) void transpose_v(const float* __restrict__ V,
                                                   float* __restrict__ Vt) {
    __shared__ float tb[32][33];
    const int bh = blockIdx.z;
    const int s0 = blockIdx.x * 32, d0 = blockIdx.y * 32;
    const int tx = threadIdx.x, ty = threadIdx.y;   // 32 x 8
    const float* src = V + (size_t)bh * S_LEN * 64;
    float* dst = Vt + (size_t)bh * 64 * S_LEN;
#pragma unroll
    for (int i = 0; i < 4; i++)
        tb[ty + i * 8][tx] = src[(size_t)(s0 + ty + i * 8) * 64 + d0 + tx];
    __syncthreads();
#pragma unroll
    for (int i = 0; i < 4; i++)
        dst[(size_t)(d0 + ty + i * 8) * S_LEN + s0 + tx] = tb[tx][ty + i * 8];
}

// ---------------- residual + LayerNorm ------------------------------------
__global__ __launch_bounds__(256) void ln_kernel(
    const float* __restrict__ x, const float* __restrict__ prj,
    const float* __restrict__ gamma, const float* __restrict__ beta,
    float* __restrict__ out)
{
    const int row = blockIdx.x;
    const int tid = threadIdx.x;

    const float4 xv = ((const float4*)(x   + (size_t)row * D_MOD))[tid];
    const float4 pv = ((const float4*)(prj + (size_t)row * D_MOD))[tid];
    float4 h;
    h.x = xv.x + pv.x; h.y = xv.y + pv.y; h.z = xv.z + pv.z; h.w = xv.w + pv.w;

    float sum = h.x + h.y + h.z + h.w;
    float ssq = h.x * h.x + h.y * h.y + h.z * h.z + h.w * h.w;
#pragma unroll
    for (int o = 16; o > 0; o >>= 1) {
        sum += __shfl_xor_sync(0xffffffffu, sum, o);
        ssq += __shfl_xor_sync(0xffffffffu, ssq, o);
    }
    __shared__ float rs[8], rq[8];
    const int warp = tid >> 5, lane = tid & 31;
    if (lane == 0) { rs[warp] = sum; rq[warp] = ssq; }
    __syncthreads();
    float ts = 0.f, tq = 0.f;
#pragma unroll
    for (int i = 0; i < 8; i++) { ts += rs[i]; tq += rq[i]; }

    const float mu   = ts * (1.f / (float)D_MOD);
    const float var  = tq * (1.f / (float)D_MOD) - mu * mu;
    const float rstd = rsqrtf(var + 1e-5f);

    const float4 gg = ((const float4*)gamma)[tid];
    const float4 bb = ((const float4*)beta)[tid];
    float4 o;
    o.x = (h.x - mu) * rstd * gg.x + bb.x;
    o.y = (h.y - mu) * rstd * gg.y + bb.y;
    o.z = (h.z - mu) * rstd * gg.z + bb.z;
    o.w = (h.w - mu) * rstd * gg.w + bb.w;
    ((float4*)(out + (size_t)row * D_MOD))[tid] = o;
}

// ---------------- launch ----------------------------------------------------
extern "C" void kernel_launch(void* const* d_in, const int* in_sizes, int n_in,
                              void* d_out, int out_size)
{
    const float* x  = (const float*)d_in[0];
    const float* Wq = (const float*)d_in[1];
    const float* bq = (const float*)d_in[2];
    const float* Wk = (const float*)d_in[3];
    const float* bk = (const float*)d_in[4];
    const float* Wv = (const float*)d_in[5];
    const float* bv = (const float*)d_in[6];
    const float* Wo = (const float*)d_in[7];
    const float* bo = (const float*)d_in[8];
    const float* ga = (const float*)d_in[9];
    const float* be = (const float*)d_in[10];
    float* out = (float*)d_out;

    float *Qp, *Kp, *Vp, *Vtp, *Cp, *Pp, *Wt, *WoT;
    cudaGetSymbolAddress((void**)&Qp,  g_Q);
    cudaGetSymbolAddress((void**)&Kp,  g_K);
    cudaGetSymbolAddress((void**)&Vp,  g_V);
    cudaGetSymbolAddress((void**)&Vtp, g_Vt);
    cudaGetSymbolAddress((void**)&Cp,  g_ctx);
    cudaGetSymbolAddress((void**)&Pp,  g_prj);
    cudaGetSymbolAddress((void**)&Wt,  g_WqkvT);
    cudaGetSymbolAddress((void**)&WoT, g_WoT);

    const int attn_smem = (2 * QTILE + 4 * KVTILE) * (int)sizeof(float);   // 139264
    cudaFuncSetAttribute(attn_tc, cudaFuncAttributeMaxDynamicSharedMemorySize, attn_smem);

    prep_weights<<<dim3(32, 32, 4), dim3(32, 8)>>>(Wq, Wk, Wv, Wo, Wt, WoT);

    gemm_mma<1><<<dim3(24, 32), 256>>>(x, Wt, bq, bk, bv, Qp, Kp, Vp);

    transpose_v<<<dim3(64, 2, NBH), dim3(32, 8)>>>(Vp, Vtp);

    attn_tc<<<dim3(S_LEN / 128, NBH), 256, attn_smem>>>(Qp, Kp, Vtp, Cp);

    gemm_mma<0><<<dim3(8, 32), 256>>>(Cp, WoT, bo, bo, bo, Pp, Pp, Pp);

    ln_kernel<<<ROWS, 256>>>(x, Pp, ga, be, out);
}

// round 6
// speedup vs baseline: 1.8750x; 1.8750x over previous
#include <cuda_runtime.h>
#include <cuda_fp16.h>
#include <cstdint>
#include <math.h>

#define S_LEN 2048
#define D_MOD 1024
#define ROWS  4096          // B*S
#define NBH   32            // B*H

// ---------------- scratch (static; no allocations) ----------
__device__ __align__(128) __half g_xh [ROWS * D_MOD];         // x in fp16
__device__ __align__(128) __half g_Wh [3 * D_MOD * D_MOD];    // QKV weights [3072][1024] K-major fp16
__device__ __align__(128) __half g_Woh[D_MOD * D_MOD];        // Wo [1024][1024] K-major fp16
__device__ __align__(128) __half g_Q  [NBH * S_LEN * 64];
__device__ __align__(128) __half g_K  [NBH * S_LEN * 64];
__device__ __align__(128) __half g_V  [NBH * S_LEN * 64];
__device__ __align__(128) __half g_Vt [NBH * 64 * S_LEN];     // [bh][dk][s]
__device__ __align__(128) __half g_ctxh[ROWS * D_MOD];        // attn out, fp16
__device__ __align__(128) float  g_prj[ROWS * D_MOD];

// ---------------- helpers ----------------
__device__ __forceinline__ uint32_t smem_u32(const void* p) {
    uint32_t a;
    asm("{ .reg .u64 t; cvta.to.shared.u64 t, %1; cvt.u32.u64 %0, t; }" : "=r"(a) : "l"(p));
    return a;
}
__device__ __forceinline__ void cp16(uint32_t dst, const void* src) {
    asm volatile("cp.async.cg.shared.global [%0], [%1], 16;" :: "r"(dst), "l"(src) : "memory");
}
#define CP_COMMIT() asm volatile("cp.async.commit_group;" ::: "memory")
#define CP_WAIT0()  asm volatile("cp.async.wait_group 0;" ::: "memory")
#define CP_WAIT1()  asm volatile("cp.async.wait_group 1;" ::: "memory")

// D += A@B, m16n8k16 fp16 in / fp32 accum (A row-major, B stored [n][k])
__device__ __forceinline__ void mma16(float* d, const uint32_t* a, const uint32_t* b) {
    asm volatile("mma.sync.aligned.m16n8k16.row.col.f32.f16.f16.f32 "
        "{%0,%1,%2,%3}, {%4,%5,%6,%7}, {%8,%9}, {%0,%1,%2,%3};"
        : "+f"(d[0]), "+f"(d[1]), "+f"(d[2]), "+f"(d[3])
        : "r"(a[0]), "r"(a[1]), "r"(a[2]), "r"(a[3]), "r"(b[0]), "r"(b[1]));
}

// ======================= fp16 mma.sync GEMM =======================
// C[4096, N] = A[4096,1024] @ W[N,1024]^T + bias.  BM=BN=128, BK=32 halves.
// smem rows: 16 data u32 + 4 pad = 20 u32 (40 halves)
#define GPAD 20

template <int QKV>
__global__ __launch_bounds__(256, 2) void gemm_h(
    const __half* __restrict__ A, const __half* __restrict__ W,
    const float* __restrict__ b0, const float* __restrict__ b1, const float* __restrict__ b2,
    __half* __restrict__ hq, __half* __restrict__ hk, __half* __restrict__ hv,
    float* __restrict__ of)
{
    __shared__ uint32_t As[2][128 * GPAD];
    __shared__ uint32_t Bs[2][128 * GPAD];

    const int tid = threadIdx.x;
    const int wid = tid >> 5, lane = tid & 31;
    const int g = lane >> 2, t = lane & 3;
    const int wm = wid & 1, wn = wid >> 1;       // warp 64 (M) x 32 (N)
    const int m0 = blockIdx.y * 128;
    const int n0 = blockIdx.x * 128;

    const uint32_t sA[2] = {smem_u32(As[0]), smem_u32(As[1])};
    const uint32_t sB[2] = {smem_u32(Bs[0]), smem_u32(Bs[1])};

    float acc[4][4][4];
#pragma unroll
    for (int i = 0; i < 4; i++)
#pragma unroll
        for (int j = 0; j < 4; j++)
#pragma unroll
            for (int r = 0; r < 4; r++) acc[i][j][r] = 0.f;

#define G_LOAD(st, kt) do {                                                       \
    _Pragma("unroll")                                                             \
    for (int i = 0; i < 2; i++) {                                                 \
        int j = tid + i * 256;                                                    \
        int r = j >> 2, cq = j & 3;                                               \
        cp16(sA[st] + (uint32_t)(r * GPAD + cq * 4) * 4,                          \
             A + (size_t)(m0 + r) * 1024 + (kt) * 32 + cq * 8);                   \
        cp16(sB[st] + (uint32_t)(r * GPAD + cq * 4) * 4,                          \
             W + (size_t)(n0 + r) * 1024 + (kt) * 32 + cq * 8);                   \
    }                                                                             \
    CP_COMMIT();                                                                  \
} while (0)

    G_LOAD(0, 0);
    for (int kt = 0; kt < 32; kt++) {
        const int st = kt & 1;
        if (kt < 31) { G_LOAD(st ^ 1, kt + 1); CP_WAIT1(); }
        else         { CP_WAIT0(); }
        __syncthreads();

        const uint32_t* Ab = As[st];
        const uint32_t* Bb = Bs[st];
#pragma unroll
        for (int ks = 0; ks < 2; ks++) {
            uint32_t af[4][4];
#pragma unroll
            for (int mt = 0; mt < 4; mt++) {
                const uint32_t* ap = Ab + (wm * 64 + mt * 16 + g) * GPAD + ks * 8 + t;
                af[mt][0] = ap[0];
                af[mt][1] = ap[8 * GPAD];
                af[mt][2] = ap[4];
                af[mt][3] = ap[8 * GPAD + 4];
            }
#pragma unroll
            for (int nt = 0; nt < 4; nt++) {
                const uint32_t* bp = Bb + (wn * 32 + nt * 8 + g) * GPAD + ks * 8 + t;
                uint32_t bf[2] = {bp[0], bp[4]};
#pragma unroll
                for (int mt = 0; mt < 4; mt++) mma16(acc[mt][nt], af[mt], bf);
            }
        }
        __syncthreads();
    }

    // epilogue
#pragma unroll
    for (int mt = 0; mt < 4; mt++) {
        const int r0 = m0 + wm * 64 + mt * 16 + g;
#pragma unroll
        for (int nt = 0; nt < 4; nt++) {
            const int col = n0 + wn * 32 + nt * 8 + 2 * t;
            if (QKV) {
                const int mat = col >> 10, nl = col & 1023;
                const float* bias = (mat == 0 ? b0 : mat == 1 ? b1 : b2);
                __half* op = (mat == 0 ? hq : mat == 1 ? hk : hv);
                const int h = nl >> 6, d = nl & 63;
                const float2 bv = *(const float2*)(bias + nl);
                const int b = r0 >> 11, s = r0 & 2047;
                __half* p = op + ((size_t)((b * 16 + h) * 2048 + s)) * 64 + d;
                *(__half2*)p = __floats2half2_rn(acc[mt][nt][0] + bv.x, acc[mt][nt][1] + bv.y);
                *(__half2*)(p + 8 * 64) = __floats2half2_rn(acc[mt][nt][2] + bv.x,
                                                            acc[mt][nt][3] + bv.y);
            } else {
                const float2 bv = *(const float2*)(b0 + col);
                float* p = of + (size_t)r0 * 1024 + col;
                *(float2*)p = make_float2(acc[mt][nt][0] + bv.x, acc[mt][nt][1] + bv.y);
                *(float2*)(p + 8 * 1024) = make_float2(acc[mt][nt][2] + bv.x,
                                                       acc[mt][nt][3] + bv.y);
            }
        }
    }
}

// ======================= fp16 flash attention =======================
// CTA: 128 queries, 8 warps (16 q-rows each). KV tiles of 64.
// smem rows: 32 data u32 (64 halves) + 4 pad = 36 u32.
#define AP   36
#define QU   (128 * AP)     // 4608 u32
#define KVU  (64 * AP)      // 2304 u32
#define ATTN_SMEM ((QU + 4 * KVU) * 4)   // 55296 bytes

__global__ __launch_bounds__(256, 2) void attn_h(
    const __half* __restrict__ Q, const __half* __restrict__ K,
    const __half* __restrict__ Vt, __half* __restrict__ Ctx)
{
    extern __shared__ uint32_t smu[];
    uint32_t* Qs = smu;                 // after qf hoist, reused as Ps
    uint32_t* Ks = smu + QU;
    uint32_t* Vs = smu + QU + 2 * KVU;

    const int bh = blockIdx.y;
    const int q0 = blockIdx.x * 128;
    const int tid = threadIdx.x;
    const int wid = tid >> 5, lane = tid & 31;
    const int g = lane >> 2, t = lane & 3;

    const __half* Qb = Q  + (size_t)bh * S_LEN * 64;
    const __half* Kb = K  + (size_t)bh * S_LEN * 64;
    const __half* Vb = Vt + (size_t)bh * 64 * S_LEN;

    const uint32_t uQ = smem_u32(Qs);
    const uint32_t uK[2] = {smem_u32(Ks), smem_u32(Ks + KVU)};
    const uint32_t uV[2] = {smem_u32(Vs), smem_u32(Vs + KVU)};

#define LOAD_K(st, kt) do { _Pragma("unroll") for (int i = 0; i < 2; i++) { \
    int j = tid + i * 256; int r = j >> 3, cq = j & 7;                      \
    cp16(uK[st] + (uint32_t)(r * AP + cq * 4) * 4,                          \
         Kb + (size_t)((kt) * 64 + r) * 64 + cq * 8); } } while (0)
#define LOAD_V(st, kt) do { _Pragma("unroll") for (int i = 0; i < 2; i++) { \
    int j = tid + i * 256; int r = j >> 3, cq = j & 7;                      \
    cp16(uV[st] + (uint32_t)(r * AP + cq * 4) * 4,                          \
         Vb + (size_t)r * S_LEN + (kt) * 64 + cq * 8); } } while (0)

    // prologue: Q + K0 + V0
#pragma unroll
    for (int i = 0; i < 4; i++) {
        int j = tid + i * 256; int r = j >> 3, cq = j & 7;
        cp16(uQ + (uint32_t)(r * AP + cq * 4) * 4, Qb + (size_t)(q0 + r) * 64 + cq * 8);
    }
    LOAD_K(0, 0); LOAD_V(0, 0); CP_COMMIT();
    CP_WAIT0();
    __syncthreads();

    const int rbase = wid * 16 + g;           // this thread's q-row (local)

    // hoist Q fragments for all 4 k16 steps (dk=64)
    uint32_t qf[4][4];
#pragma unroll
    for (int ks = 0; ks < 4; ks++) {
        const uint32_t* ap = Qs + rbase * AP + ks * 8 + t;
        qf[ks][0] = ap[0];
        qf[ks][1] = ap[8 * AP];
        qf[ks][2] = ap[4];
        qf[ks][3] = ap[8 * AP + 4];
    }
    __syncthreads();
    uint32_t* Ps = Qs;                        // Q smem now dead; reuse as P buffer

    float m0 = -1e30f, m1 = -1e30f, l0 = 0.f, l1 = 0.f;
    float oacc[8][4];
#pragma unroll
    for (int i = 0; i < 8; i++)
#pragma unroll
        for (int r = 0; r < 4; r++) oacc[i][r] = 0.f;

    for (int kt = 0; kt < 32; kt++) {
        const int st = kt & 1;
        if (kt > 0) { CP_WAIT0(); __syncthreads(); }
        if (kt < 31) { LOAD_K(st ^ 1, kt + 1); LOAD_V(st ^ 1, kt + 1); CP_COMMIT(); }

        // ---- S = Q @ K^T over dk=64 ----
        float sacc[8][4];
#pragma unroll
        for (int i = 0; i < 8; i++)
#pragma unroll
            for (int r = 0; r < 4; r++) sacc[i][r] = 0.f;

        const uint32_t* Kt = Ks + st * KVU;
#pragma unroll
        for (int ks = 0; ks < 4; ks++) {
#pragma unroll
            for (int nt = 0; nt < 8; nt++) {
                const uint32_t* bp = Kt + (nt * 8 + g) * AP + ks * 8 + t;
                uint32_t bf[2] = {bp[0], bp[4]};
                mma16(sacc[nt], qf[ks], bf);
            }
        }

        // ---- online softmax (rows rbase, rbase+8) ----
        float rmax0 = -1e30f, rmax1 = -1e30f;
#pragma unroll
        for (int nt = 0; nt < 8; nt++) {
#pragma unroll
            for (int r = 0; r < 4; r++) sacc[nt][r] *= 0.125f;
            rmax0 = fmaxf(rmax0, fmaxf(sacc[nt][0], sacc[nt][1]));
            rmax1 = fmaxf(rmax1, fmaxf(sacc[nt][2], sacc[nt][3]));
        }
        rmax0 = fmaxf(rmax0, __shfl_xor_sync(0xffffffffu, rmax0, 1));
        rmax0 = fmaxf(rmax0, __shfl_xor_sync(0xffffffffu, rmax0, 2));
        rmax1 = fmaxf(rmax1, __shfl_xor_sync(0xffffffffu, rmax1, 1));
        rmax1 = fmaxf(rmax1, __shfl_xor_sync(0xffffffffu, rmax1, 2));

        const float mn0 = fmaxf(m0, rmax0), mn1 = fmaxf(m1, rmax1);
        const float f0 = __expf(m0 - mn0), f1 = __expf(m1 - mn1);
        m0 = mn0; m1 = mn1;

        float rs0 = 0.f, rs1 = 0.f;
#pragma unroll
        for (int nt = 0; nt < 8; nt++) {
            __half2 p0 = __floats2half2_rn(__expf(sacc[nt][0] - m0), __expf(sacc[nt][1] - m0));
            __half2 p1 = __floats2half2_rn(__expf(sacc[nt][2] - m1), __expf(sacc[nt][3] - m1));
            *(__half2*)&Ps[rbase * AP + nt * 4 + t]       = p0;
            *(__half2*)&Ps[(rbase + 8) * AP + nt * 4 + t] = p1;
            const float2 q0f = __half22float2(p0), q1f = __half22float2(p1);
            rs0 += q0f.x + q0f.y; rs1 += q1f.x + q1f.y;
        }
        rs0 += __shfl_xor_sync(0xffffffffu, rs0, 1);
        rs0 += __shfl_xor_sync(0xffffffffu, rs0, 2);
        rs1 += __shfl_xor_sync(0xffffffffu, rs1, 1);
        rs1 += __shfl_xor_sync(0xffffffffu, rs1, 2);
        l0 = l0 * f0 + rs0; l1 = l1 * f1 + rs1;

#pragma unroll
        for (int nt = 0; nt < 8; nt++) {
            oacc[nt][0] *= f0; oacc[nt][1] *= f0;
            oacc[nt][2] *= f1; oacc[nt][3] *= f1;
        }
        __syncwarp();   // Ps rows are per-warp private

        // ---- O += P @ V  (V^T tile: [dk][key]) ----
        const uint32_t* Vtile = Vs + st * KVU;
#pragma unroll
        for (int ks = 0; ks < 4; ks++) {
            const uint32_t* ap = Ps + rbase * AP + ks * 8 + t;
            uint32_t af[4] = {ap[0], ap[8 * AP], ap[4], ap[8 * AP + 4]};
#pragma unroll
            for (int nt = 0; nt < 8; nt++) {
                const uint32_t* bp = Vtile + (nt * 8 + g) * AP + ks * 8 + t;
                uint32_t bf[2] = {bp[0], bp[4]};
                mma16(oacc[nt], af, bf);
            }
        }
        __syncwarp();
    }

    // ---- epilogue: ctx half [b][s][h*64+d] ----
    const float inv0 = 1.f / l0, inv1 = 1.f / l1;
    const int b = bh >> 4, h = bh & 15;
    const int row0 = q0 + rbase;
    __half* base0 = Ctx + ((size_t)(b * 2048 + row0)) * 1024 + h * 64;
#pragma unroll
    for (int nt = 0; nt < 8; nt++) {
        const int col = nt * 8 + 2 * t;
        *(__half2*)(base0 + col) = __floats2half2_rn(oacc[nt][0] * inv0, oacc[nt][1] * inv0);
        *(__half2*)(base0 + 8 * 1024 + col) = __floats2half2_rn(oacc[nt][2] * inv1,
                                                                oacc[nt][3] * inv1);
    }
}

// ======================= prep kernels =======================
__global__ __launch_bounds__(256) void cvt_x(const float* __restrict__ x,
                                             __half* __restrict__ xh) {
    const int i = blockIdx.x * 256 + threadIdx.x;
    float4 v = ((const float4*)x)[i];
    ((__half2*)xh)[i * 2]     = __floats2half2_rn(v.x, v.y);
    ((__half2*)xh)[i * 2 + 1] = __floats2half2_rn(v.z, v.w);
}

__global__ __launch_bounds__(256) void prep_weights(
    const float* __restrict__ Wq, const float* __restrict__ Wk,
    const float* __restrict__ Wv, const float* __restrict__ Wo,
    __half* __restrict__ Wh, __half* __restrict__ Woh)
{
    __shared__ float tb[32][33];
    const int z = blockIdx.z;
    const float* src = (z == 0) ? Wq : (z == 1) ? Wk : (z == 2) ? Wv : Wo;
    __half* dst = (z < 3) ? (Wh + (size_t)z * D_MOD * D_MOD) : Woh;
    const int k0 = blockIdx.x * 32, n0 = blockIdx.y * 32;
    const int tx = threadIdx.x, ty = threadIdx.y;   // 32 x 8
#pragma unroll
    for (int i = 0; i < 4; i++)
        tb[ty + i * 8][tx] = src[(size_t)(k0 + ty + i * 8) * D_MOD + n0 + tx];
    __syncthreads();
#pragma unroll
    for (int i = 0; i < 4; i++)
        dst[(size_t)(n0 + ty + i * 8) * D_MOD + k0 + tx] = __float2half_rn(tb[tx][ty + i * 8]);
}

// V [bh][s][64] -> Vt [bh][64][s], fp16
__global__ __launch_bounds__(256) void transpose_v(const __half* __restrict__ V,
                                                   __half* __restrict__ Vt) {
    __shared__ __half tb[32][36];
    const int bh = blockIdx.z;
    const int s0 = blockIdx.x * 32, d0 = blockIdx.y * 32;
    const int tx = threadIdx.x, ty = threadIdx.y;   // 32 x 8
    const __half* src = V + (size_t)bh * S_LEN * 64;
    __half* dst = Vt + (size_t)bh * 64 * S_LEN;
#pragma unroll
    for (int i = 0; i < 4; i++)
        tb[ty + i * 8][tx] = src[(size_t)(s0 + ty + i * 8) * 64 + d0 + tx];
    __syncthreads();
#pragma unroll
    for (int i = 0; i < 4; i++)
        dst[(size_t)(d0 + ty + i * 8) * S_LEN + s0 + tx] = tb[tx][ty + i * 8];
}

// ---------------- residual + LayerNorm ------------------------------------
__global__ __launch_bounds__(256) void ln_kernel(
    const float* __restrict__ x, const float* __restrict__ prj,
    const float* __restrict__ gamma, const float* __restrict__ beta,
    float* __restrict__ out)
{
    const int row = blockIdx.x;
    const int tid = threadIdx.x;

    const float4 xv = ((const float4*)(x   + (size_t)row * D_MOD))[tid];
    const float4 pv = ((const float4*)(prj + (size_t)row * D_MOD))[tid];
    float4 h;
    h.x = xv.x + pv.x; h.y = xv.y + pv.y; h.z = xv.z + pv.z; h.w = xv.w + pv.w;

    float sum = h.x + h.y + h.z + h.w;
    float ssq = h.x * h.x + h.y * h.y + h.z * h.z + h.w * h.w;
#pragma unroll
    for (int o = 16; o > 0; o >>= 1) {
        sum += __shfl_xor_sync(0xffffffffu, sum, o);
        ssq += __shfl_xor_sync(0xffffffffu, ssq, o);
    }
    __shared__ float rs[8], rq[8];
    const int warp = tid >> 5, lane = tid & 31;
    if (lane == 0) { rs[warp] = sum; rq[warp] = ssq; }
    __syncthreads();
    float ts = 0.f, tq = 0.f;
#pragma unroll
    for (int i = 0; i < 8; i++) { ts += rs[i]; tq += rq[i]; }

    const float mu   = ts * (1.f / (float)D_MOD);
    const float var  = tq * (1.f / (float)D_MOD) - mu * mu;
    const float rstd = rsqrtf(var + 1e-5f);

    const float4 gg = ((const float4*)gamma)[tid];
    const float4 bb = ((const float4*)beta)[tid];
    float4 o;
    o.x = (h.x - mu) * rstd * gg.x + bb.x;
    o.y = (h.y - mu) * rstd * gg.y + bb.y;
    o.z = (h.z - mu) * rstd * gg.z + bb.z;
    o.w = (h.w - mu) * rstd * gg.w + bb.w;
    ((float4*)(out + (size_t)row * D_MOD))[tid] = o;
}

// ---------------- launch ----------------------------------------------------
extern "C" void kernel_launch(void* const* d_in, const int* in_sizes, int n_in,
                              void* d_out, int out_size)
{
    const float* x  = (const float*)d_in[0];
    const float* Wq = (const float*)d_in[1];
    const float* bq = (const float*)d_in[2];
    const float* Wk = (const float*)d_in[3];
    const float* bk = (const float*)d_in[4];
    const float* Wv = (const float*)d_in[5];
    const float* bv = (const float*)d_in[6];
    const float* Wo = (const float*)d_in[7];
    const float* bo = (const float*)d_in[8];
    const float* ga = (const float*)d_in[9];
    const float* be = (const float*)d_in[10];
    float* out = (float*)d_out;

    __half *Xh, *Wh, *Woh, *Qp, *Kp, *Vp, *Vtp, *Ch;
    float *Pp;
    cudaGetSymbolAddress((void**)&Xh,  g_xh);
    cudaGetSymbolAddress((void**)&Wh,  g_Wh);
    cudaGetSymbolAddress((void**)&Woh, g_Woh);
    cudaGetSymbolAddress((void**)&Qp,  g_Q);
    cudaGetSymbolAddress((void**)&Kp,  g_K);
    cudaGetSymbolAddress((void**)&Vp,  g_V);
    cudaGetSymbolAddress((void**)&Vtp, g_Vt);
    cudaGetSymbolAddress((void**)&Ch,  g_ctxh);
    cudaGetSymbolAddress((void**)&Pp,  g_prj);

    cudaFuncSetAttribute(attn_h, cudaFuncAttributeMaxDynamicSharedMemorySize, ATTN_SMEM);

    cvt_x<<<ROWS * D_MOD / 1024, 256>>>(x, Xh);
    prep_weights<<<dim3(32, 32, 4), dim3(32, 8)>>>(Wq, Wk, Wv, Wo, Wh, Woh);

    gemm_h<1><<<dim3(24, 32), 256>>>(Xh, Wh, bq, bk, bv, Qp, Kp, Vp, nullptr);

    transpose_v<<<dim3(64, 2, NBH), dim3(32, 8)>>>(Vp, Vtp);

    attn_h<<<dim3(S_LEN / 128, NBH), 256, ATTN_SMEM>>>(Qp, Kp, Vtp, Ch);

    gemm_h<0><<<dim3(8, 32), 256>>>(Ch, Woh, bo, bo, bo, nullptr, nullptr, nullptr, Pp);

    ln_kernel<<<ROWS, 256>>>(x, Pp, ga, be, out);
}